// round 12
// baseline (speedup 1.0000x reference)
#include <cuda_runtime.h>
#include <cstdint>
#include <cstddef>

// ---------------- problem constants ----------------
#define BB 128
#define FF 512
#define TT 256
#define UU 1024

// ---------------- GEMM tiling ----------------
#define CTA_M 128
#define CTA_N 128
#define KC    32            // k per chunk (4 ksteps of 8)
#define NCHUNK (FF / KC)    // 16
#define NTHREADS 256        // 8 warps: 2(M) x 4(N), warp tile 64x32

#define FLAG_DELTA 4e-3f    // proven safe (rel_err 0.0 in R6/R9/R10)
#define EXACT_BAND 5e-5
#define FLAG_CAP   (1u << 20)

// ---------------- scratch (device globals) ----------------
__device__ float g_a_perm[(size_t)64 * 64 * 32 * 4];   // W fragment-permuted fp32
__device__ float g_wt[(size_t)UU * FF];                // W^T  [U][F]
__device__ float g_xt[(size_t)BB * TT * FF];           // X^T  [B][T][F] (written by GEMM)
__device__ unsigned int g_flag_count;
__device__ unsigned int g_flag_list[FLAG_CAP];         // b[18:25)|u[8:18)|t[0:8)

// ---------------- helpers ----------------
__device__ __forceinline__ void cp16(uint32_t dst, const void* src) {
    asm volatile("cp.async.cg.shared.global [%0], [%1], 16;" :: "r"(dst), "l"(src));
}
__device__ __forceinline__ void cp_commit() { asm volatile("cp.async.commit_group;"); }
__device__ __forceinline__ void cp_wait1() { asm volatile("cp.async.wait_group 1;"); }
__device__ __forceinline__ void cp_wait0() { asm volatile("cp.async.wait_group 0;"); }

__device__ __forceinline__ void mma_tf32(float* c, const float4& a, const float2& b) {
    asm volatile(
        "mma.sync.aligned.m16n8k8.row.col.f32.tf32.tf32.f32 "
        "{%0,%1,%2,%3}, {%4,%5,%6,%7}, {%8,%9}, {%0,%1,%2,%3};"
        : "+f"(c[0]), "+f"(c[1]), "+f"(c[2]), "+f"(c[3])
        : "r"(__float_as_uint(a.x)), "r"(__float_as_uint(a.y)),
          "r"(__float_as_uint(a.z)), "r"(__float_as_uint(a.w)),
          "r"(__float_as_uint(b.x)), "r"(__float_as_uint(b.y)));
}

// ---------------- pre-pass: fragment-permute W (fp32) ----------------
__global__ __launch_bounds__(256)
void prep_w_kernel(const float* __restrict__ w) {
    const int idx = blockIdx.x * 256 + threadIdx.x;     // < 131072
    const int lane = idx & 31;
    const int mc   = (idx >> 5) & 63;
    const int kc   = idx >> 11;
    const int m = mc * 16 + (lane >> 2);
    const int k = kc * 8 + (lane & 3);
    float4 v;
    v.x = w[(size_t)k * UU + m];
    v.y = w[(size_t)k * UU + m + 8];
    v.z = w[(size_t)(k + 4) * UU + m];
    v.w = w[(size_t)(k + 4) * UU + m + 8];
    ((float4*)g_a_perm)[idx] = v;
    if (idx == 0) g_flag_count = 0;
}

__global__ __launch_bounds__(256)
void transpose_w_kernel(const float* __restrict__ w) {  // [F][U] -> [U][F]
    __shared__ float tile[32][33];
    const int u0 = blockIdx.x * 32, f0 = blockIdx.y * 32;
    const int tx = threadIdx.x, ty = threadIdx.y;       // 32 x 8
#pragma unroll
    for (int r = 0; r < 32; r += 8)
        tile[ty + r][tx] = w[(size_t)(f0 + ty + r) * UU + u0 + tx];
    __syncthreads();
#pragma unroll
    for (int r = 0; r < 32; r += 8)
        g_wt[(size_t)(u0 + ty + r) * FF + f0 + tx] = tile[tx][ty + r];
}

// ---------------- GEMM (unchanged from R9) ----------------
#define A_OFF      0
#define A_STAGE    16384
#define B_OFF      32768
#define B_STAGE    17408
#define B_ROWF     136
#define SMEM_TOTAL (32768 + 2 * B_STAGE)   // 67584

__global__ __launch_bounds__(NTHREADS, 2)
void snn_mma_gemm(const float* __restrict__ x, float* __restrict__ out) {
    extern __shared__ __align__(1024) char smem[];
    const uint32_t sb = (uint32_t)__cvta_generic_to_shared(smem);

    const int tid  = threadIdx.x;
    const int lane = tid & 31;
    const int wid  = tid >> 5;
    const int wm   = wid & 1;
    const int wn   = wid >> 1;
    const int nx   = blockIdx.x;
    const int mx   = blockIdx.y;
    const int b    = blockIdx.z;
    const int t0   = nx * CTA_N;
    const int mc0  = mx * 8;

    const float* xb = x + (size_t)b * FF * TT;

    auto issue = [&](int c, int s) {
        const uint32_t ast = sb + A_OFF + s * A_STAGE;
#pragma unroll
        for (int j = 0; j < 4; j++) {
            const int o = tid + j * 256;
            const int kt = o >> 8;
            const int off = o & 255;
            const size_t srcf = ((size_t)(c * 4 + kt) * 64 + mc0) * 128 + (size_t)off * 4;
            cp16(ast + o * 16, g_a_perm + srcf);
        }
        const uint32_t bst = sb + B_OFF + s * B_STAGE;
#pragma unroll
        for (int j = 0; j < 4; j++) {
            const int o = tid + j * 256;
            const int row = o >> 5;
            const int col = o & 31;
            cp16(bst + row * 544 + col * 16,
                 xb + ((size_t)(c * KC + row)) * TT + t0 + col * 4);
        }
        cp_commit();
    };

    float acc[4][4][4];
#pragma unroll
    for (int mt = 0; mt < 4; mt++)
#pragma unroll
        for (int nt = 0; nt < 4; nt++)
#pragma unroll
            for (int q = 0; q < 4; q++) acc[mt][nt][q] = 0.0f;

    issue(0, 0);
    issue(1, 1);

#pragma unroll 1
    for (int c = 0; c < NCHUNK; c++) {
        if (c == NCHUNK - 1) cp_wait0(); else cp_wait1();
        __syncthreads();

        const int s = c & 1;
        const float*  rawB = (const float*)(smem + B_OFF + s * B_STAGE);
        const float4* As   = (const float4*)(smem + A_OFF + s * A_STAGE);

        // fused X transpose: CTA mx == (c & 7) writes this tile to g_xt
        if (mx == (c & 7) && tid < CTA_N) {
            const int n = tid;
            float* orow = g_xt + ((size_t)b * TT + t0 + n) * FF + c * KC;
            float4 v;
#pragma unroll
            for (int kq = 0; kq < 8; kq++) {
                v.x = rawB[(kq * 4 + 0) * B_ROWF + n];
                v.y = rawB[(kq * 4 + 1) * B_ROWF + n];
                v.z = rawB[(kq * 4 + 2) * B_ROWF + n];
                v.w = rawB[(kq * 4 + 3) * B_ROWF + n];
                *(float4*)(orow + kq * 4) = v;
            }
        }

#pragma unroll
        for (int kt = 0; kt < 4; kt++) {
            float4 fa[4];
            float2 fb[4];
#pragma unroll
            for (int mt = 0; mt < 4; mt++)
                fa[mt] = As[(kt * 8 + wm * 4 + mt) * 32 + lane];
            const int kb = kt * 8 + (lane & 3);
            const int nb = lane >> 2;
#pragma unroll
            for (int nt = 0; nt < 4; nt++) {
                const int n = wn * 32 + nt * 8 + nb;
                fb[nt].x = rawB[kb * B_ROWF + n];
                fb[nt].y = rawB[(kb + 4) * B_ROWF + n];
            }
#pragma unroll
            for (int mt = 0; mt < 4; mt++)
#pragma unroll
                for (int nt = 0; nt < 4; nt++)
                    mma_tf32(acc[mt][nt], fa[mt], fb[nt]);
        }

        __syncthreads();
        if (c + 2 < NCHUNK) issue(c + 2, s);
    }

    const int m_base = mx * CTA_M + wm * 64 + (lane >> 2);
    const int t_base = t0 + wn * 32 + (lane & 3) * 2;
#pragma unroll
    for (int mt = 0; mt < 4; mt++) {
#pragma unroll
        for (int nt = 0; nt < 4; nt++) {
            const int m = m_base + mt * 16;
            const int t = t_base + nt * 8;
#pragma unroll
            for (int h = 0; h < 2; h++) {
                const int mm = m + h * 8;
                const float v0 = acc[mt][nt][h * 2 + 0];
                const float v1 = acc[mt][nt][h * 2 + 1];
                float2 r;
                r.x = v0 > 1.0f ? 1.0f : 0.0f;
                r.y = v1 > 1.0f ? 1.0f : 0.0f;
                *(float2*)(out + ((size_t)b * UU + mm) * TT + t) = r;
                if (fabsf(v0 - 1.0f) < FLAG_DELTA) {
                    unsigned idx = atomicAdd(&g_flag_count, 1u);
                    if (idx < FLAG_CAP)
                        g_flag_list[idx] = ((unsigned)b << 18) | ((unsigned)mm << 8) | (unsigned)t;
                }
                if (fabsf(v1 - 1.0f) < FLAG_DELTA) {
                    unsigned idx = atomicAdd(&g_flag_count, 1u);
                    if (idx < FLAG_CAP)
                        g_flag_list[idx] = ((unsigned)b << 18) | ((unsigned)mm << 8) | (unsigned)(t + 1);
                }
            }
        }
    }
}

// ---------------- fixup: one THREAD per flagged element ----------------
// Tier 1: fp64 dot, 4 independent accumulator chains, contiguous per-thread rows.
// Tier 2: |s - 1| <= EXACT_BAND -> exact sequential fp32 chain (reference order).
__global__ __launch_bounds__(256)
void fixup_kernel(float* __restrict__ out) {
    const unsigned n = min(g_flag_count, (unsigned)FLAG_CAP);
    const unsigned stride = gridDim.x * blockDim.x;
    for (unsigned i = blockIdx.x * blockDim.x + threadIdx.x; i < n; i += stride) {
        const unsigned code = g_flag_list[i];
        const int b = code >> 18;
        const int u = (code >> 8) & 1023;
        const int t = code & 255;
        const float4* wr = (const float4*)(g_wt + (size_t)u * FF);
        const float4* xr = (const float4*)(g_xt + ((size_t)b * TT + t) * FF);

        double s0 = 0.0, s1 = 0.0, s2 = 0.0, s3 = 0.0;
#pragma unroll 8
        for (int q = 0; q < FF / 4; q += 4) {      // 128 float4 pairs, 4 chains
            const float4 a0 = wr[q + 0], b0 = xr[q + 0];
            const float4 a1 = wr[q + 1], b1 = xr[q + 1];
            const float4 a2 = wr[q + 2], b2 = xr[q + 2];
            const float4 a3 = wr[q + 3], b3 = xr[q + 3];
            s0 += (double)a0.x * b0.x + (double)a0.y * b0.y
                + (double)a0.z * b0.z + (double)a0.w * b0.w;
            s1 += (double)a1.x * b1.x + (double)a1.y * b1.y
                + (double)a1.z * b1.z + (double)a1.w * b1.w;
            s2 += (double)a2.x * b2.x + (double)a2.y * b2.y
                + (double)a2.z * b2.z + (double)a2.w * b2.w;
            s3 += (double)a3.x * b3.x + (double)a3.y * b3.y
                + (double)a3.z * b3.z + (double)a3.w * b3.w;
        }
        const double s = (s0 + s1) + (s2 + s3);

        float r;
        if (fabs(s - 1.0) > EXACT_BAND) {
            r = (s > 1.0) ? 1.0f : 0.0f;
        } else {
            // rare: exact sequential fp32 chain in reference f-order
            const float* wf = g_wt + (size_t)u * FF;
            const float* xf = g_xt + ((size_t)b * TT + t) * FF;
            float acc = 0.0f;
#pragma unroll 16
            for (int f = 0; f < FF; f++)
                acc = __fmaf_rn(wf[f], xf[f], acc);
            r = (acc > 1.0f) ? 1.0f : 0.0f;
        }
        out[((size_t)b * UU + u) * TT + t] = r;
    }
}

// ---------------- host side ----------------
extern "C" void kernel_launch(void* const* d_in, const int* in_sizes, int n_in,
                              void* d_out, int out_size) {
    const float* x = (const float*)d_in[0];   // [B, F, T]
    const float* w = (const float*)d_in[1];   // [F, U]
    if (n_in >= 2 && in_sizes[0] == FF * UU && in_sizes[1] == BB * FF * TT) {
        const float* t = x; x = w; w = t;
    }
    float* out = (float*)d_out;

    prep_w_kernel<<<131072 / 256, 256>>>(w);
    transpose_w_kernel<<<dim3(UU / 32, FF / 32), dim3(32, 8)>>>(w);

    cudaFuncSetAttribute(snn_mma_gemm, cudaFuncAttributeMaxDynamicSharedMemorySize,
                         SMEM_TOTAL);
    snn_mma_gemm<<<dim3(TT / CTA_N, UU / CTA_M, BB), NTHREADS, SMEM_TOTAL>>>(x, out);

    fixup_kernel<<<512, 256>>>(out);
}

// round 13
// speedup vs baseline: 1.0686x; 1.0686x over previous
#include <cuda_runtime.h>
#include <cstdint>
#include <cstddef>

// ---------------- problem constants ----------------
#define BB 128
#define FF 512
#define TT 256
#define UU 1024

// ---------------- GEMM tiling ----------------
#define CTA_M 128
#define CTA_N 128
#define KC    32            // k per chunk (4 ksteps of 8)
#define NCHUNK (FF / KC)    // 16
#define NTHREADS 256        // 8 warps: 2(M) x 4(N), warp tile 64x32

#define FLAG_DELTA 4e-3f    // proven safe (rel_err 0.0 in R6/R9/R10/R12)
#define EXACT_BAND 5e-5
#define FLAG_CAP   (1u << 20)

// ---------------- scratch (device globals) ----------------
__device__ float g_a_perm[(size_t)64 * 64 * 32 * 4];   // W fragment-permuted fp32
__device__ float g_wt[(size_t)UU * FF];                // W^T  [U][F]
__device__ float g_xt[(size_t)BB * TT * FF];           // X^T  [B][T][F] (written by GEMM)
__device__ unsigned int g_flag_count;
__device__ unsigned int g_flag_list[FLAG_CAP];         // b[18:25)|u[8:18)|t[0:8)

// ---------------- helpers ----------------
__device__ __forceinline__ void cp16(uint32_t dst, const void* src) {
    asm volatile("cp.async.cg.shared.global [%0], [%1], 16;" :: "r"(dst), "l"(src));
}
__device__ __forceinline__ void cp_commit() { asm volatile("cp.async.commit_group;"); }
__device__ __forceinline__ void cp_wait1() { asm volatile("cp.async.wait_group 1;"); }
__device__ __forceinline__ void cp_wait0() { asm volatile("cp.async.wait_group 0;"); }

__device__ __forceinline__ void mma_tf32(float* c, const float4& a, const float2& b) {
    asm volatile(
        "mma.sync.aligned.m16n8k8.row.col.f32.tf32.tf32.f32 "
        "{%0,%1,%2,%3}, {%4,%5,%6,%7}, {%8,%9}, {%0,%1,%2,%3};"
        : "+f"(c[0]), "+f"(c[1]), "+f"(c[2]), "+f"(c[3])
        : "r"(__float_as_uint(a.x)), "r"(__float_as_uint(a.y)),
          "r"(__float_as_uint(a.z)), "r"(__float_as_uint(a.w)),
          "r"(__float_as_uint(b.x)), "r"(__float_as_uint(b.y)));
}

// ---------------- pre-pass: fragment-permute W (fp32) ----------------
__global__ __launch_bounds__(256)
void prep_w_kernel(const float* __restrict__ w) {
    const int idx = blockIdx.x * 256 + threadIdx.x;     // < 131072
    const int lane = idx & 31;
    const int mc   = (idx >> 5) & 63;
    const int kc   = idx >> 11;
    const int m = mc * 16 + (lane >> 2);
    const int k = kc * 8 + (lane & 3);
    float4 v;
    v.x = w[(size_t)k * UU + m];
    v.y = w[(size_t)k * UU + m + 8];
    v.z = w[(size_t)(k + 4) * UU + m];
    v.w = w[(size_t)(k + 4) * UU + m + 8];
    ((float4*)g_a_perm)[idx] = v;
    if (idx == 0) g_flag_count = 0;
}

__global__ __launch_bounds__(256)
void transpose_w_kernel(const float* __restrict__ w) {  // [F][U] -> [U][F]
    __shared__ float tile[32][33];
    const int u0 = blockIdx.x * 32, f0 = blockIdx.y * 32;
    const int tx = threadIdx.x, ty = threadIdx.y;       // 32 x 8
#pragma unroll
    for (int r = 0; r < 32; r += 8)
        tile[ty + r][tx] = w[(size_t)(f0 + ty + r) * UU + u0 + tx];
    __syncthreads();
#pragma unroll
    for (int r = 0; r < 32; r += 8)
        g_wt[(size_t)(u0 + ty + r) * FF + f0 + tx] = tile[tx][ty + r];
}

// ---------------- GEMM (unchanged from R9) ----------------
#define A_OFF      0
#define A_STAGE    16384
#define B_OFF      32768
#define B_STAGE    17408
#define B_ROWF     136
#define SMEM_TOTAL (32768 + 2 * B_STAGE)   // 67584

__global__ __launch_bounds__(NTHREADS, 2)
void snn_mma_gemm(const float* __restrict__ x, float* __restrict__ out) {
    extern __shared__ __align__(1024) char smem[];
    const uint32_t sb = (uint32_t)__cvta_generic_to_shared(smem);

    const int tid  = threadIdx.x;
    const int lane = tid & 31;
    const int wid  = tid >> 5;
    const int wm   = wid & 1;
    const int wn   = wid >> 1;
    const int nx   = blockIdx.x;
    const int mx   = blockIdx.y;
    const int b    = blockIdx.z;
    const int t0   = nx * CTA_N;
    const int mc0  = mx * 8;

    const float* xb = x + (size_t)b * FF * TT;

    auto issue = [&](int c, int s) {
        const uint32_t ast = sb + A_OFF + s * A_STAGE;
#pragma unroll
        for (int j = 0; j < 4; j++) {
            const int o = tid + j * 256;
            const int kt = o >> 8;
            const int off = o & 255;
            const size_t srcf = ((size_t)(c * 4 + kt) * 64 + mc0) * 128 + (size_t)off * 4;
            cp16(ast + o * 16, g_a_perm + srcf);
        }
        const uint32_t bst = sb + B_OFF + s * B_STAGE;
#pragma unroll
        for (int j = 0; j < 4; j++) {
            const int o = tid + j * 256;
            const int row = o >> 5;
            const int col = o & 31;
            cp16(bst + row * 544 + col * 16,
                 xb + ((size_t)(c * KC + row)) * TT + t0 + col * 4);
        }
        cp_commit();
    };

    float acc[4][4][4];
#pragma unroll
    for (int mt = 0; mt < 4; mt++)
#pragma unroll
        for (int nt = 0; nt < 4; nt++)
#pragma unroll
            for (int q = 0; q < 4; q++) acc[mt][nt][q] = 0.0f;

    issue(0, 0);
    issue(1, 1);

#pragma unroll 1
    for (int c = 0; c < NCHUNK; c++) {
        if (c == NCHUNK - 1) cp_wait0(); else cp_wait1();
        __syncthreads();

        const int s = c & 1;
        const float*  rawB = (const float*)(smem + B_OFF + s * B_STAGE);
        const float4* As   = (const float4*)(smem + A_OFF + s * A_STAGE);

        // fused X transpose: CTA mx == (c & 7) writes this tile to g_xt
        if (mx == (c & 7) && tid < CTA_N) {
            const int n = tid;
            float* orow = g_xt + ((size_t)b * TT + t0 + n) * FF + c * KC;
            float4 v;
#pragma unroll
            for (int kq = 0; kq < 8; kq++) {
                v.x = rawB[(kq * 4 + 0) * B_ROWF + n];
                v.y = rawB[(kq * 4 + 1) * B_ROWF + n];
                v.z = rawB[(kq * 4 + 2) * B_ROWF + n];
                v.w = rawB[(kq * 4 + 3) * B_ROWF + n];
                *(float4*)(orow + kq * 4) = v;
            }
        }

#pragma unroll
        for (int kt = 0; kt < 4; kt++) {
            float4 fa[4];
            float2 fb[4];
#pragma unroll
            for (int mt = 0; mt < 4; mt++)
                fa[mt] = As[(kt * 8 + wm * 4 + mt) * 32 + lane];
            const int kb = kt * 8 + (lane & 3);
            const int nb = lane >> 2;
#pragma unroll
            for (int nt = 0; nt < 4; nt++) {
                const int n = wn * 32 + nt * 8 + nb;
                fb[nt].x = rawB[kb * B_ROWF + n];
                fb[nt].y = rawB[(kb + 4) * B_ROWF + n];
            }
#pragma unroll
            for (int mt = 0; mt < 4; mt++)
#pragma unroll
                for (int nt = 0; nt < 4; nt++)
                    mma_tf32(acc[mt][nt], fa[mt], fb[nt]);
        }

        __syncthreads();
        if (c + 2 < NCHUNK) issue(c + 2, s);
    }

    const int m_base = mx * CTA_M + wm * 64 + (lane >> 2);
    const int t_base = t0 + wn * 32 + (lane & 3) * 2;
#pragma unroll
    for (int mt = 0; mt < 4; mt++) {
#pragma unroll
        for (int nt = 0; nt < 4; nt++) {
            const int m = m_base + mt * 16;
            const int t = t_base + nt * 8;
#pragma unroll
            for (int h = 0; h < 2; h++) {
                const int mm = m + h * 8;
                const float v0 = acc[mt][nt][h * 2 + 0];
                const float v1 = acc[mt][nt][h * 2 + 1];
                float2 r;
                r.x = v0 > 1.0f ? 1.0f : 0.0f;
                r.y = v1 > 1.0f ? 1.0f : 0.0f;
                *(float2*)(out + ((size_t)b * UU + mm) * TT + t) = r;
                if (fabsf(v0 - 1.0f) < FLAG_DELTA) {
                    unsigned idx = atomicAdd(&g_flag_count, 1u);
                    if (idx < FLAG_CAP)
                        g_flag_list[idx] = ((unsigned)b << 18) | ((unsigned)mm << 8) | (unsigned)t;
                }
                if (fabsf(v1 - 1.0f) < FLAG_DELTA) {
                    unsigned idx = atomicAdd(&g_flag_count, 1u);
                    if (idx < FLAG_CAP)
                        g_flag_list[idx] = ((unsigned)b << 18) | ((unsigned)mm << 8) | (unsigned)(t + 1);
                }
            }
        }
    }
}

// ---------------- fixup: 8-lane GROUP per flagged element ----------------
// Coalesced (each group load = one 128B line) AND parallel (4 elements/warp,
// ~15k warps). Tier 1: fp64 group dot + 3 shfl.xor reduce (deterministic).
// Tier 2: |s-1| <= EXACT_BAND -> exact sequential fp32 chain (reference order).
__global__ __launch_bounds__(256)
void fixup_kernel(float* __restrict__ out) {
    const unsigned n = min(g_flag_count, (unsigned)FLAG_CAP);
    const int lane = threadIdx.x & 31;
    const int grp  = lane >> 3;          // group 0..3 within warp
    const int gl   = lane & 7;           // lane within group
    const unsigned warp_global = (blockIdx.x * blockDim.x + threadIdx.x) >> 5;
    const unsigned nwarps = (gridDim.x * blockDim.x) >> 5;

    for (unsigned base = warp_global * 4; base < n; base += nwarps * 4) {
        const unsigned e = base + grp;
        const bool active = (e < n);
        const unsigned code = g_flag_list[active ? e : (n - 1)];
        const int b = code >> 18;
        const int u = (code >> 8) & 1023;
        const int t = code & 255;
        const float4* wr = (const float4*)(g_wt + (size_t)u * FF);
        const float4* xr = (const float4*)(g_xt + ((size_t)b * TT + t) * FF);

        // per-lane partial dot over stripes gl, gl+8, ..., gl+120 (16 float4 each)
        double s0 = 0.0, s1 = 0.0;
#pragma unroll 4
        for (int j = 0; j < 16; j += 2) {
            const float4 a0 = wr[gl + 8 * j],       c0 = xr[gl + 8 * j];
            const float4 a1 = wr[gl + 8 * (j + 1)], c1 = xr[gl + 8 * (j + 1)];
            s0 += (double)a0.x * c0.x + (double)a0.y * c0.y
                + (double)a0.z * c0.z + (double)a0.w * c0.w;
            s1 += (double)a1.x * c1.x + (double)a1.y * c1.y
                + (double)a1.z * c1.z + (double)a1.w * c1.w;
        }
        double s = s0 + s1;
        // reduce across the 8 lanes of the group (xor 1,2,4 stays in-group)
        s += __shfl_xor_sync(0xFFFFFFFFu, s, 1);
        s += __shfl_xor_sync(0xFFFFFFFFu, s, 2);
        s += __shfl_xor_sync(0xFFFFFFFFu, s, 4);

        if (active && gl == 0) {
            float r;
            if (fabs(s - 1.0) > EXACT_BAND) {
                r = (s > 1.0) ? 1.0f : 0.0f;
            } else {
                // rare: exact sequential fp32 chain in reference f-order (L1-hot)
                const float* wf = g_wt + (size_t)u * FF;
                const float* xf = g_xt + ((size_t)b * TT + t) * FF;
                float acc = 0.0f;
#pragma unroll 16
                for (int f = 0; f < FF; f++)
                    acc = __fmaf_rn(wf[f], xf[f], acc);
                r = (acc > 1.0f) ? 1.0f : 0.0f;
            }
            out[((size_t)b * UU + u) * TT + t] = r;
        }
    }
}

// ---------------- host side ----------------
extern "C" void kernel_launch(void* const* d_in, const int* in_sizes, int n_in,
                              void* d_out, int out_size) {
    const float* x = (const float*)d_in[0];   // [B, F, T]
    const float* w = (const float*)d_in[1];   // [F, U]
    if (n_in >= 2 && in_sizes[0] == FF * UU && in_sizes[1] == BB * FF * TT) {
        const float* t = x; x = w; w = t;
    }
    float* out = (float*)d_out;

    prep_w_kernel<<<131072 / 256, 256>>>(w);
    transpose_w_kernel<<<dim3(UU / 32, FF / 32), dim3(32, 8)>>>(w);

    cudaFuncSetAttribute(snn_mma_gemm, cudaFuncAttributeMaxDynamicSharedMemorySize,
                         SMEM_TOTAL);
    snn_mma_gemm<<<dim3(TT / CTA_N, UU / CTA_M, BB), NTHREADS, SMEM_TOTAL>>>(x, out);

    fixup_kernel<<<2048, 256>>>(out);
}

// round 15
// speedup vs baseline: 1.1775x; 1.1019x over previous
#include <cuda_runtime.h>
#include <cstdint>
#include <cstddef>

// ---------------- problem constants ----------------
#define BB 128
#define FF 512
#define TT 256
#define UU 1024

// ---------------- GEMM tiling ----------------
#define CTA_M 128
#define CTA_N 128
#define KC    32            // k per chunk (4 ksteps of 8)
#define NCHUNK (FF / KC)    // 16
#define NTHREADS 256        // 8 warps: 2(M) x 4(N), warp tile 64x32

#define FLAG_DELTA 4e-3f    // proven safe (rel_err 0.0 in R6/R9/R10/R12/R13)
#define EXACT_BAND 5e-5
#define RARE_CAP   (1u << 18)
#define QCAP       512      // per-CTA smem queue entries

// ---------------- scratch (device globals) ----------------
__device__ float g_a_perm[(size_t)64 * 64 * 32 * 4];   // W fragment-permuted fp32
__device__ float g_wt[(size_t)UU * FF];                // W^T  [U][F]
__device__ unsigned int g_rare_count;
__device__ unsigned int g_rare_list[RARE_CAP];         // b[18:25)|u[8:18)|t[0:8)

// ---------------- helpers ----------------
__device__ __forceinline__ void cp16(uint32_t dst, const void* src) {
    asm volatile("cp.async.cg.shared.global [%0], [%1], 16;" :: "r"(dst), "l"(src));
}
__device__ __forceinline__ void cp_commit() { asm volatile("cp.async.commit_group;"); }
__device__ __forceinline__ void cp_wait1() { asm volatile("cp.async.wait_group 1;"); }
__device__ __forceinline__ void cp_wait0() { asm volatile("cp.async.wait_group 0;"); }

__device__ __forceinline__ void mma_tf32(float* c, const float4& a, const float2& b) {
    asm volatile(
        "mma.sync.aligned.m16n8k8.row.col.f32.tf32.tf32.f32 "
        "{%0,%1,%2,%3}, {%4,%5,%6,%7}, {%8,%9}, {%0,%1,%2,%3};"
        : "+f"(c[0]), "+f"(c[1]), "+f"(c[2]), "+f"(c[3])
        : "r"(__float_as_uint(a.x)), "r"(__float_as_uint(a.y)),
          "r"(__float_as_uint(a.z)), "r"(__float_as_uint(a.w)),
          "r"(__float_as_uint(b.x)), "r"(__float_as_uint(b.y)));
}

// ---------------- pre-pass: fragment-permute W (fp32) ----------------
__global__ __launch_bounds__(256)
void prep_w_kernel(const float* __restrict__ w) {
    const int idx = blockIdx.x * 256 + threadIdx.x;     // < 131072
    const int lane = idx & 31;
    const int mc   = (idx >> 5) & 63;
    const int kc   = idx >> 11;
    const int m = mc * 16 + (lane >> 2);
    const int k = kc * 8 + (lane & 3);
    float4 v;
    v.x = w[(size_t)k * UU + m];
    v.y = w[(size_t)k * UU + m + 8];
    v.z = w[(size_t)(k + 4) * UU + m];
    v.w = w[(size_t)(k + 4) * UU + m + 8];
    ((float4*)g_a_perm)[idx] = v;
    if (idx == 0) g_rare_count = 0;
}

__global__ __launch_bounds__(256)
void transpose_w_kernel(const float* __restrict__ w) {  // [F][U] -> [U][F]
    __shared__ float tile[32][33];
    const int u0 = blockIdx.x * 32, f0 = blockIdx.y * 32;
    const int tx = threadIdx.x, ty = threadIdx.y;       // 32 x 8
#pragma unroll
    for (int r = 0; r < 32; r += 8)
        tile[ty + r][tx] = w[(size_t)(f0 + ty + r) * UU + u0 + tx];
    __syncthreads();
#pragma unroll
    for (int r = 0; r < 32; r += 8)
        g_wt[(size_t)(u0 + ty + r) * FF + f0 + tx] = tile[tx][ty + r];
}

// ---------------- GEMM + in-epilogue tier-1 fixup ----------------
#define A_OFF      0
#define A_STAGE    16384
#define B_OFF      32768
#define B_STAGE    17408
#define B_ROWF     136
#define Q_OFF      (32768 + 2 * B_STAGE)          // queue after stage buffers
#define SMEM_TOTAL (Q_OFF + QCAP * 2)             // 68608

__global__ __launch_bounds__(NTHREADS, 2)
void snn_mma_gemm(const float* __restrict__ x, float* __restrict__ out) {
    extern __shared__ __align__(1024) char smem[];
    const uint32_t sb = (uint32_t)__cvta_generic_to_shared(smem);
    unsigned short* queue = (unsigned short*)(smem + Q_OFF);
    __shared__ int q_cnt;

    const int tid  = threadIdx.x;
    const int lane = tid & 31;
    const int wid  = tid >> 5;
    const int wm   = wid & 1;
    const int wn   = wid >> 1;
    const int nx   = blockIdx.x;
    const int mx   = blockIdx.y;
    const int b    = blockIdx.z;
    const int t0   = nx * CTA_N;
    const int mc0  = mx * 8;

    const float* xb = x + (size_t)b * FF * TT;

    if (tid == 0) q_cnt = 0;

    auto issue = [&](int c, int s) {
        const uint32_t ast = sb + A_OFF + s * A_STAGE;
#pragma unroll
        for (int j = 0; j < 4; j++) {
            const int o = tid + j * 256;
            const int kt = o >> 8;
            const int off = o & 255;
            const size_t srcf = ((size_t)(c * 4 + kt) * 64 + mc0) * 128 + (size_t)off * 4;
            cp16(ast + o * 16, g_a_perm + srcf);
        }
        const uint32_t bst = sb + B_OFF + s * B_STAGE;
#pragma unroll
        for (int j = 0; j < 4; j++) {
            const int o = tid + j * 256;
            const int row = o >> 5;
            const int col = o & 31;
            cp16(bst + row * 544 + col * 16,
                 xb + ((size_t)(c * KC + row)) * TT + t0 + col * 4);
        }
        cp_commit();
    };

    float acc[4][4][4];
#pragma unroll
    for (int mt = 0; mt < 4; mt++)
#pragma unroll
        for (int nt = 0; nt < 4; nt++)
#pragma unroll
            for (int q = 0; q < 4; q++) acc[mt][nt][q] = 0.0f;

    issue(0, 0);
    issue(1, 1);

#pragma unroll 1
    for (int c = 0; c < NCHUNK; c++) {
        if (c == NCHUNK - 1) cp_wait0(); else cp_wait1();
        __syncthreads();

        const int s = c & 1;
        const float*  rawB = (const float*)(smem + B_OFF + s * B_STAGE);
        const float4* As   = (const float4*)(smem + A_OFF + s * A_STAGE);

#pragma unroll
        for (int kt = 0; kt < 4; kt++) {
            float4 fa[4];
            float2 fb[4];
#pragma unroll
            for (int mt = 0; mt < 4; mt++)
                fa[mt] = As[(kt * 8 + wm * 4 + mt) * 32 + lane];
            const int kb = kt * 8 + (lane & 3);
            const int nb = lane >> 2;
#pragma unroll
            for (int nt = 0; nt < 4; nt++) {
                const int n = wn * 32 + nt * 8 + nb;
                fb[nt].x = rawB[kb * B_ROWF + n];
                fb[nt].y = rawB[(kb + 4) * B_ROWF + n];
            }
#pragma unroll
            for (int mt = 0; mt < 4; mt++)
#pragma unroll
                for (int nt = 0; nt < 4; nt++)
                    mma_tf32(acc[mt][nt], fa[mt], fb[nt]);
        }

        __syncthreads();
        if (c + 2 < NCHUNK) issue(c + 2, s);
    }

    // ---- epilogue: threshold + store + enqueue near-threshold locally ----
    const int ml_base = wm * 64 + (lane >> 2);          // local m within CTA
    const int tl_base = wn * 32 + (lane & 3) * 2;       // local t within CTA
#pragma unroll
    for (int mt = 0; mt < 4; mt++) {
#pragma unroll
        for (int nt = 0; nt < 4; nt++) {
            const int ml0 = ml_base + mt * 16;
            const int tl0 = tl_base + nt * 8;
#pragma unroll
            for (int h = 0; h < 2; h++) {
                const int ml = ml0 + h * 8;
                const float v0 = acc[mt][nt][h * 2 + 0];
                const float v1 = acc[mt][nt][h * 2 + 1];
                float2 r;
                r.x = v0 > 1.0f ? 1.0f : 0.0f;
                r.y = v1 > 1.0f ? 1.0f : 0.0f;
                *(float2*)(out + ((size_t)b * UU + mx * CTA_M + ml) * TT + t0 + tl0) = r;
#pragma unroll
                for (int e = 0; e < 2; e++) {
                    const float v = e ? v1 : v0;
                    if (fabsf(v - 1.0f) < FLAG_DELTA) {
                        const int qi = atomicAdd(&q_cnt, 1);
                        const int tl = tl0 + e;
                        if (qi < QCAP) {
                            queue[qi] = (unsigned short)((ml << 7) | tl);
                        } else {            // overflow: exact path handles it
                            const unsigned gi = atomicAdd(&g_rare_count, 1u);
                            if (gi < RARE_CAP)
                                g_rare_list[gi] = ((unsigned)b << 18)
                                    | ((unsigned)(mx * CTA_M + ml) << 8)
                                    | (unsigned)(t0 + tl);
                        }
                    }
                }
            }
        }
    }

    __syncthreads();                        // queue complete; orders default stores

    // ---- tier-1: warp-per-queued-element fp64 recheck (L2-hot operands) ----
    const int qn = min(q_cnt, QCAP);
#pragma unroll 1
    for (int q = wid; q < qn; q += 8) {
        const int code = queue[q];
        const int ml = code >> 7, tl = code & 127;
        const int u  = mx * CTA_M + ml;
        const int tg = t0 + tl;
        const float4* wrow = (const float4*)(g_wt + (size_t)u * FF);
        const float*  xcol = x + (size_t)b * FF * TT + tg;

        double s = 0.0;
#pragma unroll
        for (int j = 0; j < 4; j++) {
            const float4 wv = wrow[lane + 32 * j];
            const int f0_ = 4 * (lane + 32 * j);
            const float x0 = __ldg(xcol + (size_t)(f0_ + 0) * TT);
            const float x1 = __ldg(xcol + (size_t)(f0_ + 1) * TT);
            const float x2 = __ldg(xcol + (size_t)(f0_ + 2) * TT);
            const float x3 = __ldg(xcol + (size_t)(f0_ + 3) * TT);
            s += (double)wv.x * x0 + (double)wv.y * x1
               + (double)wv.z * x2 + (double)wv.w * x3;
        }
#pragma unroll
        for (int o = 16; o > 0; o >>= 1)
            s += __shfl_xor_sync(0xFFFFFFFFu, s, o);

        if (lane == 0) {
            if (fabs(s - 1.0) > EXACT_BAND) {
                out[((size_t)b * UU + u) * TT + tg] = (s > 1.0) ? 1.0f : 0.0f;
            } else {
                const unsigned gi = atomicAdd(&g_rare_count, 1u);
                if (gi < RARE_CAP)
                    g_rare_list[gi] = ((unsigned)b << 18) | ((unsigned)u << 8)
                                    | (unsigned)tg;
            }
        }
    }
}

// ---------------- tier-2: exact sequential fp32 chain on rare elements ----
#define RARE_WARPS 8
__global__ __launch_bounds__(RARE_WARPS * 32)
void rare_kernel(const float* __restrict__ x, float* __restrict__ out) {
    __shared__ float ws[RARE_WARPS][FF];
    __shared__ float xs[RARE_WARPS][FF];
    const unsigned n = min(g_rare_count, (unsigned)RARE_CAP);
    const int lane = threadIdx.x & 31;
    const int wrp  = threadIdx.x >> 5;
    const unsigned gw = blockIdx.x * RARE_WARPS + wrp;
    const unsigned nw = gridDim.x * RARE_WARPS;
    for (unsigned i = gw; i < n; i += nw) {
        const unsigned code = g_rare_list[i];
        const int b = code >> 18;
        const int u = (code >> 8) & 1023;
        const int t = code & 255;
#pragma unroll
        for (int j = 0; j < FF / 32; j++) {
            const int f = lane + j * 32;
            ws[wrp][f] = g_wt[(size_t)u * FF + f];
            xs[wrp][f] = x[((size_t)b * FF + f) * TT + t];
        }
        __syncwarp();
        if (lane == 0) {
            float acc = 0.0f;                  // exact sequential fp32 chain
#pragma unroll 16
            for (int f = 0; f < FF; f++)
                acc = __fmaf_rn(ws[wrp][f], xs[wrp][f], acc);
            out[((size_t)b * UU + u) * TT + t] = acc > 1.0f ? 1.0f : 0.0f;
        }
        __syncwarp();
    }
}

// ---------------- host side ----------------
extern "C" void kernel_launch(void* const* d_in, const int* in_sizes, int n_in,
                              void* d_out, int out_size) {
    const float* x = (const float*)d_in[0];   // [B, F, T]
    const float* w = (const float*)d_in[1];   // [F, U]
    if (n_in >= 2 && in_sizes[0] == FF * UU && in_sizes[1] == BB * FF * TT) {
        const float* t = x; x = w; w = t;
    }
    float* out = (float*)d_out;

    prep_w_kernel<<<131072 / 256, 256>>>(w);
    transpose_w_kernel<<<dim3(UU / 32, FF / 32), dim3(32, 8)>>>(w);

    cudaFuncSetAttribute(snn_mma_gemm, cudaFuncAttributeMaxDynamicSharedMemorySize,
                         SMEM_TOTAL);
    snn_mma_gemm<<<dim3(TT / CTA_N, UU / CTA_M, BB), NTHREADS, SMEM_TOTAL>>>(x, out);

    rare_kernel<<<256, RARE_WARPS * 32>>>(x, out);
}

// round 16
// speedup vs baseline: 1.6931x; 1.4379x over previous
#include <cuda_runtime.h>
#include <cstdint>
#include <cstddef>

// ---------------- problem constants ----------------
#define BB 128
#define FF 512
#define TT 256
#define UU 1024

// ---------------- GEMM tiling ----------------
#define CTA_M 128
#define CTA_N 128
#define KC    32            // k per chunk (4 ksteps of 8)
#define NCHUNK (FF / KC)    // 16
#define NTHREADS 256        // 8 warps: 2(M) x 4(N), warp tile 64x32

#define FLAG_DELTA 1.5e-3f  // 5 sigma of measured single-pass tf32 error
#define EXACT_BAND 2e-5     // ~15x fp32-sequential-chain error
#define RARE_CAP   (1u << 18)
#define QCAP       512      // per-CTA smem queue entries

// ---------------- scratch (device globals) ----------------
__device__ float g_a_perm[(size_t)64 * 64 * 32 * 4];   // W fragment-permuted fp32
__device__ float g_wt[(size_t)UU * FF];                // W^T  [U][F]
__device__ unsigned int g_rare_count;
__device__ unsigned int g_rare_list[RARE_CAP];         // b[18:25)|u[8:18)|t[0:8)

// ---------------- helpers ----------------
__device__ __forceinline__ void cp16(uint32_t dst, const void* src) {
    asm volatile("cp.async.cg.shared.global [%0], [%1], 16;" :: "r"(dst), "l"(src));
}
__device__ __forceinline__ void cp_commit() { asm volatile("cp.async.commit_group;"); }
__device__ __forceinline__ void cp_wait1() { asm volatile("cp.async.wait_group 1;"); }
__device__ __forceinline__ void cp_wait0() { asm volatile("cp.async.wait_group 0;"); }

__device__ __forceinline__ void mma_tf32(float* c, const float4& a, const float2& b) {
    asm volatile(
        "mma.sync.aligned.m16n8k8.row.col.f32.tf32.tf32.f32 "
        "{%0,%1,%2,%3}, {%4,%5,%6,%7}, {%8,%9}, {%0,%1,%2,%3};"
        : "+f"(c[0]), "+f"(c[1]), "+f"(c[2]), "+f"(c[3])
        : "r"(__float_as_uint(a.x)), "r"(__float_as_uint(a.y)),
          "r"(__float_as_uint(a.z)), "r"(__float_as_uint(a.w)),
          "r"(__float_as_uint(b.x)), "r"(__float_as_uint(b.y)));
}

// ---------------- pre-pass: fragment-permute W (fp32) ----------------
__global__ __launch_bounds__(256)
void prep_w_kernel(const float* __restrict__ w) {
    const int idx = blockIdx.x * 256 + threadIdx.x;     // < 131072
    const int lane = idx & 31;
    const int mc   = (idx >> 5) & 63;
    const int kc   = idx >> 11;
    const int m = mc * 16 + (lane >> 2);
    const int k = kc * 8 + (lane & 3);
    float4 v;
    v.x = w[(size_t)k * UU + m];
    v.y = w[(size_t)k * UU + m + 8];
    v.z = w[(size_t)(k + 4) * UU + m];
    v.w = w[(size_t)(k + 4) * UU + m + 8];
    ((float4*)g_a_perm)[idx] = v;
    if (idx == 0) g_rare_count = 0;
}

__global__ __launch_bounds__(256)
void transpose_w_kernel(const float* __restrict__ w) {  // [F][U] -> [U][F]
    __shared__ float tile[32][33];
    const int u0 = blockIdx.x * 32, f0 = blockIdx.y * 32;
    const int tx = threadIdx.x, ty = threadIdx.y;       // 32 x 8
#pragma unroll
    for (int r = 0; r < 32; r += 8)
        tile[ty + r][tx] = w[(size_t)(f0 + ty + r) * UU + u0 + tx];
    __syncthreads();
#pragma unroll
    for (int r = 0; r < 32; r += 8)
        g_wt[(size_t)(u0 + ty + r) * FF + f0 + tx] = tile[tx][ty + r];
}

// ---------------- GEMM + in-epilogue tier-1 fixup ----------------
#define A_OFF      0
#define A_STAGE    16384
#define B_OFF      32768
#define B_STAGE    17408
#define B_ROWF     136
#define Q_OFF      (32768 + 2 * B_STAGE)          // queue after stage buffers
#define SMEM_TOTAL (Q_OFF + QCAP * 2)             // 68608

__global__ __launch_bounds__(NTHREADS, 2)
void snn_mma_gemm(const float* __restrict__ x, float* __restrict__ out) {
    extern __shared__ __align__(1024) char smem[];
    const uint32_t sb = (uint32_t)__cvta_generic_to_shared(smem);
    unsigned short* queue = (unsigned short*)(smem + Q_OFF);
    __shared__ int q_cnt;

    const int tid  = threadIdx.x;
    const int lane = tid & 31;
    const int wid  = tid >> 5;
    const int wm   = wid & 1;
    const int wn   = wid >> 1;
    const int nx   = blockIdx.x;
    const int mx   = blockIdx.y;
    const int b    = blockIdx.z;
    const int t0   = nx * CTA_N;
    const int mc0  = mx * 8;

    const float* xb = x + (size_t)b * FF * TT;

    if (tid == 0) q_cnt = 0;

    auto issue = [&](int c, int s) {
        const uint32_t ast = sb + A_OFF + s * A_STAGE;
#pragma unroll
        for (int j = 0; j < 4; j++) {
            const int o = tid + j * 256;
            const int kt = o >> 8;
            const int off = o & 255;
            const size_t srcf = ((size_t)(c * 4 + kt) * 64 + mc0) * 128 + (size_t)off * 4;
            cp16(ast + o * 16, g_a_perm + srcf);
        }
        const uint32_t bst = sb + B_OFF + s * B_STAGE;
#pragma unroll
        for (int j = 0; j < 4; j++) {
            const int o = tid + j * 256;
            const int row = o >> 5;
            const int col = o & 31;
            cp16(bst + row * 544 + col * 16,
                 xb + ((size_t)(c * KC + row)) * TT + t0 + col * 4);
        }
        cp_commit();
    };

    float acc[4][4][4];
#pragma unroll
    for (int mt = 0; mt < 4; mt++)
#pragma unroll
        for (int nt = 0; nt < 4; nt++)
#pragma unroll
            for (int q = 0; q < 4; q++) acc[mt][nt][q] = 0.0f;

    issue(0, 0);
    issue(1, 1);

#pragma unroll 1
    for (int c = 0; c < NCHUNK; c++) {
        if (c == NCHUNK - 1) cp_wait0(); else cp_wait1();
        __syncthreads();

        const int s = c & 1;
        const float*  rawB = (const float*)(smem + B_OFF + s * B_STAGE);
        const float4* As   = (const float4*)(smem + A_OFF + s * A_STAGE);

#pragma unroll
        for (int kt = 0; kt < 4; kt++) {
            float4 fa[4];
            float2 fb[4];
#pragma unroll
            for (int mt = 0; mt < 4; mt++)
                fa[mt] = As[(kt * 8 + wm * 4 + mt) * 32 + lane];
            const int kb = kt * 8 + (lane & 3);
            const int nb = lane >> 2;
#pragma unroll
            for (int nt = 0; nt < 4; nt++) {
                const int n = wn * 32 + nt * 8 + nb;
                fb[nt].x = rawB[kb * B_ROWF + n];
                fb[nt].y = rawB[(kb + 4) * B_ROWF + n];
            }
#pragma unroll
            for (int mt = 0; mt < 4; mt++)
#pragma unroll
                for (int nt = 0; nt < 4; nt++)
                    mma_tf32(acc[mt][nt], fa[mt], fb[nt]);
        }

        __syncthreads();
        if (c + 2 < NCHUNK) issue(c + 2, s);
    }

    // ---- epilogue: threshold + store + enqueue near-threshold locally ----
    const int ml_base = wm * 64 + (lane >> 2);          // local m within CTA
    const int tl_base = wn * 32 + (lane & 3) * 2;       // local t within CTA
#pragma unroll
    for (int mt = 0; mt < 4; mt++) {
#pragma unroll
        for (int nt = 0; nt < 4; nt++) {
            const int ml0 = ml_base + mt * 16;
            const int tl0 = tl_base + nt * 8;
#pragma unroll
            for (int h = 0; h < 2; h++) {
                const int ml = ml0 + h * 8;
                const float v0 = acc[mt][nt][h * 2 + 0];
                const float v1 = acc[mt][nt][h * 2 + 1];
                float2 r;
                r.x = v0 > 1.0f ? 1.0f : 0.0f;
                r.y = v1 > 1.0f ? 1.0f : 0.0f;
                *(float2*)(out + ((size_t)b * UU + mx * CTA_M + ml) * TT + t0 + tl0) = r;
#pragma unroll
                for (int e = 0; e < 2; e++) {
                    const float v = e ? v1 : v0;
                    if (fabsf(v - 1.0f) < FLAG_DELTA) {
                        const int qi = atomicAdd(&q_cnt, 1);
                        const int tl = tl0 + e;
                        if (qi < QCAP) {
                            queue[qi] = (unsigned short)((ml << 7) | tl);
                        } else {            // overflow: exact path handles it
                            const unsigned gi = atomicAdd(&g_rare_count, 1u);
                            if (gi < RARE_CAP)
                                g_rare_list[gi] = ((unsigned)b << 18)
                                    | ((unsigned)(mx * CTA_M + ml) << 8)
                                    | (unsigned)(t0 + tl);
                        }
                    }
                }
            }
        }
    }

    __syncthreads();                        // queue complete; orders default stores

    // ---- tier-1: warp-per-queued-element fp64 recheck (L2-hot operands) ----
    const int qn = min(q_cnt, QCAP);
#pragma unroll 1
    for (int q = wid; q < qn; q += 8) {
        const int code = queue[q];
        const int ml = code >> 7, tl = code & 127;
        const int u  = mx * CTA_M + ml;
        const int tg = t0 + tl;
        const float4* wrow = (const float4*)(g_wt + (size_t)u * FF);
        const float*  xcol = x + (size_t)b * FF * TT + tg;

        double s = 0.0;
#pragma unroll
        for (int j = 0; j < 4; j++) {
            const float4 wv = wrow[lane + 32 * j];
            const int f0_ = 4 * (lane + 32 * j);
            const float x0 = __ldg(xcol + (size_t)(f0_ + 0) * TT);
            const float x1 = __ldg(xcol + (size_t)(f0_ + 1) * TT);
            const float x2 = __ldg(xcol + (size_t)(f0_ + 2) * TT);
            const float x3 = __ldg(xcol + (size_t)(f0_ + 3) * TT);
            s += (double)wv.x * x0 + (double)wv.y * x1
               + (double)wv.z * x2 + (double)wv.w * x3;
        }
#pragma unroll
        for (int o = 16; o > 0; o >>= 1)
            s += __shfl_xor_sync(0xFFFFFFFFu, s, o);

        if (lane == 0) {
            if (fabs(s - 1.0) > EXACT_BAND) {
                out[((size_t)b * UU + u) * TT + tg] = (s > 1.0) ? 1.0f : 0.0f;
            } else {
                const unsigned gi = atomicAdd(&g_rare_count, 1u);
                if (gi < RARE_CAP)
                    g_rare_list[gi] = ((unsigned)b << 18) | ((unsigned)u << 8)
                                    | (unsigned)tg;
            }
        }
    }
}

// ---------------- tier-2: exact sequential fp32 chain on rare elements ----
#define RARE_WARPS 8
__global__ __launch_bounds__(RARE_WARPS * 32)
void rare_kernel(const float* __restrict__ x, float* __restrict__ out) {
    __shared__ float ws[RARE_WARPS][FF];
    __shared__ float xs[RARE_WARPS][FF];
    const unsigned n = min(g_rare_count, (unsigned)RARE_CAP);
    const int lane = threadIdx.x & 31;
    const int wrp  = threadIdx.x >> 5;
    const unsigned gw = blockIdx.x * RARE_WARPS + wrp;
    const unsigned nw = gridDim.x * RARE_WARPS;
    for (unsigned i = gw; i < n; i += nw) {
        const unsigned code = g_rare_list[i];
        const int b = code >> 18;
        const int u = (code >> 8) & 1023;
        const int t = code & 255;
#pragma unroll
        for (int j = 0; j < FF / 32; j++) {
            const int f = lane + j * 32;
            ws[wrp][f] = g_wt[(size_t)u * FF + f];
            xs[wrp][f] = x[((size_t)b * FF + f) * TT + t];
        }
        __syncwarp();
        if (lane == 0) {
            float acc = 0.0f;                  // exact sequential fp32 chain
#pragma unroll 16
            for (int f = 0; f < FF; f++)
                acc = __fmaf_rn(ws[wrp][f], xs[wrp][f], acc);
            out[((size_t)b * UU + u) * TT + t] = acc > 1.0f ? 1.0f : 0.0f;
        }
        __syncwarp();
    }
}

// ---------------- host side ----------------
extern "C" void kernel_launch(void* const* d_in, const int* in_sizes, int n_in,
                              void* d_out, int out_size) {
    const float* x = (const float*)d_in[0];   // [B, F, T]
    const float* w = (const float*)d_in[1];   // [F, U]
    if (n_in >= 2 && in_sizes[0] == FF * UU && in_sizes[1] == BB * FF * TT) {
        const float* t = x; x = w; w = t;
    }
    float* out = (float*)d_out;

    prep_w_kernel<<<131072 / 256, 256>>>(w);
    transpose_w_kernel<<<dim3(UU / 32, FF / 32), dim3(32, 8)>>>(w);

    cudaFuncSetAttribute(snn_mma_gemm, cudaFuncAttributeMaxDynamicSharedMemorySize,
                         SMEM_TOTAL);
    snn_mma_gemm<<<dim3(TT / CTA_N, UU / CTA_M, BB), NTHREADS, SMEM_TOTAL>>>(x, out);

    rare_kernel<<<256, RARE_WARPS * 32>>>(x, out);
}